// round 11
// baseline (speedup 1.0000x reference)
#include <cuda_runtime.h>
#include <cuda_fp16.h>
#include <cstdint>
#include <cstddef>

#define N_    8192
#define IND   256
#define OUTD  64
#define NS    64                 // j splits -> 4096 attention blocks
#define JSPL  (N_ / NS)          // 128 j per block
#define CH    (JSPL / 32)        // 4 chunks
#define L2E   1.4426950408889634f

// ---------------- device scratch (no runtime allocation allowed) ----------------
__device__ __align__(16) float  g_h  [N_ * OUTD];
__device__ __align__(16) uint4  g_hB4[(N_ / 16) * 128];      // B fragments uint4-paired, 1MB
__device__ __align__(16) float4 g_f2p[(N_ / 16) * 4];        // permuted f2*log2e
__device__ __align__(16) float  g_f1 [N_];
__device__ __align__(16) float  g_f1L[N_];                   // f1*log2e
__device__ __align__(16) float  g_f2 [N_];
__device__ __align__(16) float  g_V  [N_ * OUTD];
__device__ __align__(16) float  g_S  [N_];
__device__ uint32_t g_maxkey;
__device__ float    g_maxf2L;

typedef unsigned long long ull;

// ---------------- helpers ----------------
__device__ __forceinline__ ull pk2(float x) {
    ull u; asm("mov.b64 %0, {%1, %1};" : "=l"(u) : "r"(__float_as_uint(x))); return u;
}
__device__ __forceinline__ void ffma2(ull& d, ull a, ull b) {
    asm("fma.rn.f32x2 %0, %1, %2, %0;" : "+l"(d) : "l"(a), "l"(b));
}
__device__ __forceinline__ float2 upk(ull u) {
    float2 f; asm("mov.b64 {%0, %1}, %2;" : "=f"(f.x), "=f"(f.y) : "l"(u)); return f;
}
__device__ __forceinline__ void red2(float* p, float a, float b) {
    asm volatile("red.global.add.v2.f32 [%0], {%1, %2};"
                 :: "l"(p), "f"(a), "f"(b) : "memory");
}
__device__ __forceinline__ void red1(float* p, float a) {
    asm volatile("red.global.add.f32 [%0], %1;" :: "l"(p), "f"(a) : "memory");
}
__device__ __forceinline__ void redmax(uint32_t* p, uint32_t v) {
    asm volatile("red.global.max.u32 [%0], %1;" :: "l"(p), "r"(v) : "memory");
}
__device__ __forceinline__ float ex2f(float x) {
    float r; asm("ex2.approx.f32 %0, %1;" : "=f"(r) : "f"(x)); return r;
}
__device__ __forceinline__ void mma16(float* d, const uint32_t* a, uint32_t b0, uint32_t b1) {
    asm volatile("mma.sync.aligned.m16n8k16.row.col.f32.f16.f16.f32 "
                 "{%0,%1,%2,%3}, {%4,%5,%6,%7}, {%8,%9}, {%0,%1,%2,%3};"
                 : "+f"(d[0]), "+f"(d[1]), "+f"(d[2]), "+f"(d[3])
                 : "r"(a[0]), "r"(a[1]), "r"(a[2]), "r"(a[3]), "r"(b0), "r"(b1));
}

// ---------------- launch 1: zero V/S + maxkey reset ----------------
__global__ void k_zero() {
    int i = blockIdx.x * blockDim.x + threadIdx.x;
    if (i == 0) g_maxkey = 0u;
    float4 z = make_float4(0.f, 0.f, 0.f, 0.f);
    if (i < (N_ * OUTD) / 4) reinterpret_cast<float4*>(g_V)[i] = z;
    else                     reinterpret_cast<float4*>(g_S)[i - (N_ * OUTD) / 4] = z;
}

// ---------------- launch 2: h = input @ W (f32x2) + fused f1/f2 + red.max ----------------
__global__ void __launch_bounds__(256) k_h(const float* __restrict__ input,
                                           const float* __restrict__ W,
                                           const float* __restrict__ a) {
    extern __shared__ float sm[];
    float* in_s = sm;
    float* W_s  = sm + 64 * 260;
    int t = threadIdx.x;
    int rowBase = blockIdx.x * 64;

#pragma unroll
    for (int m = 0; m < 16; m++) {
        int idx4 = t + 256 * m;
        *reinterpret_cast<float4*>(&W_s[4 * idx4]) =
            *reinterpret_cast<const float4*>(&W[4 * idx4]);
    }
#pragma unroll
    for (int m = 0; m < 16; m++) {
        int idx4 = t + 256 * m;
        int r = idx4 >> 6, k4 = (idx4 & 63) * 4;
        *reinterpret_cast<float4*>(&in_s[r * 260 + k4]) =
            *reinterpret_cast<const float4*>(&input[(size_t)(rowBase + r) * IND + k4]);
    }
    __syncthreads();

    int ty = t >> 3, tx = t & 7;
    ull acc[2][4];
#pragma unroll
    for (int r = 0; r < 2; r++)
#pragma unroll
        for (int g = 0; g < 4; g++) acc[r][g] = 0ull;

#pragma unroll 8
    for (int k = 0; k < IND; k++) {
        ulonglong2 wa = *reinterpret_cast<const ulonglong2*>(&W_s[k * 64 + 4 * tx]);
        ulonglong2 wb = *reinterpret_cast<const ulonglong2*>(&W_s[k * 64 + 32 + 4 * tx]);
#pragma unroll
        for (int r = 0; r < 2; r++) {
            ull iv = pk2(in_s[(2 * ty + r) * 260 + k]);
            ffma2(acc[r][0], iv, wa.x); ffma2(acc[r][1], iv, wa.y);
            ffma2(acc[r][2], iv, wb.x); ffma2(acc[r][3], iv, wb.y);
        }
    }

    float4 A1a = *reinterpret_cast<const float4*>(&a[4 * tx]);
    float4 A1b = *reinterpret_cast<const float4*>(&a[32 + 4 * tx]);
    float4 A2a = *reinterpret_cast<const float4*>(&a[OUTD + 4 * tx]);
    float4 A2b = *reinterpret_cast<const float4*>(&a[OUTD + 32 + 4 * tx]);

#pragma unroll
    for (int r = 0; r < 2; r++) {
        int row = rowBase + 2 * ty + r;
        float2 p0 = upk(acc[r][0]), p1 = upk(acc[r][1]);
        float2 p2 = upk(acc[r][2]), p3 = upk(acc[r][3]);
        *reinterpret_cast<float4*>(&g_h[row * OUTD + 4 * tx]) = make_float4(p0.x, p0.y, p1.x, p1.y);
        *reinterpret_cast<float4*>(&g_h[row * OUTD + 32 + 4 * tx]) = make_float4(p2.x, p2.y, p3.x, p3.y);

        float s1 = p0.x * A1a.x + p0.y * A1a.y + p1.x * A1a.z + p1.y * A1a.w
                 + p2.x * A1b.x + p2.y * A1b.y + p3.x * A1b.z + p3.y * A1b.w;
        float s2 = p0.x * A2a.x + p0.y * A2a.y + p1.x * A2a.z + p1.y * A2a.w
                 + p2.x * A2b.x + p2.y * A2b.y + p3.x * A2b.z + p3.y * A2b.w;
#pragma unroll
        for (int off = 1; off < 8; off <<= 1) {
            s1 += __shfl_xor_sync(0xFFFFFFFFu, s1, off);
            s2 += __shfl_xor_sync(0xFFFFFFFFu, s2, off);
        }
        if (tx == 0) {
            g_f1[row]  = s1;
            g_f1L[row] = s1 * L2E;
            g_f2[row]  = s2;
            uint32_t u = __float_as_uint(s2);
            uint32_t key = u ^ (uint32_t)(((int)u >> 31) | 0x80000000);
            redmax(&g_maxkey, key);
        }
    }
}

// ---------------- launch 3: pack permuted B fragments + f2p + decode max ----------------
__global__ void __launch_bounds__(256) k_prep() {
    __shared__ float tile[64][65];
    int t = threadIdx.x, b = blockIdx.x;
    int jBase = b * 64;

    if (b == 0 && t == 0) {
        uint32_t k = g_maxkey;
        uint32_t u = (k & 0x80000000u) ? (k ^ 0x80000000u) : ~k;
        g_maxf2L = __uint_as_float(u) * L2E;
    }

    if (t < 16) {
        int j16r = t >> 2, fc = t & 3;
        int j = jBase + j16r * 16 + 4 * fc;
        float4 v;
        v.x = g_f2[j]     * L2E;
        v.y = g_f2[j + 1] * L2E;
        v.z = g_f2[j + 2] * L2E;
        v.w = g_f2[j + 3] * L2E;
        g_f2p[(jBase / 16 + j16r) * 4 + fc] = v;
    }

#pragma unroll
    for (int m = 0; m < 4; m++) {
        int idx = t + 256 * m;
        int j = idx >> 4, c4 = (idx & 15) * 4;
        float4 v = *reinterpret_cast<const float4*>(&g_h[(size_t)(jBase + j) * OUTD + c4]);
        tile[j][c4] = v.x; tile[j][c4 + 1] = v.y; tile[j][c4 + 2] = v.z; tile[j][c4 + 3] = v.w;
    }
    __syncthreads();

#pragma unroll
    for (int m = 0; m < 2; m++) {
        int idx = t + 256 * m;            // 0..511 = j16r(4) x qq(4) x lane(32)
        int j16r = idx >> 7;
        int qq   = (idx >> 5) & 3;
        int lane = idx & 31;
        int fr = lane >> 2, fc = lane & 3;
        int j0 = j16r * 16 + 4 * fc;
        int n1 = qq * 8 + fr;
        int n2 = (qq + 4) * 8 + fr;
        __half2 lo1 = __floats2half2_rn(tile[j0][n1],     tile[j0 + 1][n1]);
        __half2 hi1 = __floats2half2_rn(tile[j0 + 2][n1], tile[j0 + 3][n1]);
        __half2 lo2 = __floats2half2_rn(tile[j0][n2],     tile[j0 + 1][n2]);
        __half2 hi2 = __floats2half2_rn(tile[j0 + 2][n2], tile[j0 + 3][n2]);
        uint4 pkt;
        pkt.x = *reinterpret_cast<uint32_t*>(&lo1);
        pkt.y = *reinterpret_cast<uint32_t*>(&hi1);
        pkt.z = *reinterpret_cast<uint32_t*>(&lo2);
        pkt.w = *reinterpret_cast<uint32_t*>(&hi2);
        g_hB4[((jBase / 16 + j16r) * 4 + qq) * 32 + lane] = pkt;
    }
}

// ---------------- launch 4 (PROFILED): smem-B register-fragment attention ----------------
// NS=64: 128 j per block, 4 chunks; B tile 16KB; IMAD/LOP mask (no I2F).
__global__ void __launch_bounds__(256, 3) k_attn(const int* __restrict__ adj) {
    __shared__ uint4  sB[1024];   // 16KB B fragments for this block's 128 j
    __shared__ float4 sF[32];     // 512B f2p

    int t = threadIdx.x;
    int wid = t >> 5, lane = t & 31;
    int fr = lane >> 2, fc = lane & 3;
    int mrow   = blockIdx.y * 128 + wid * 16;
    int jStart = blockIdx.x * JSPL;

    // stage B + f2 tiles (one-time, L2-resident source)
    {
        const uint4* gB = g_hB4 + (size_t)(jStart / 16) * 128;
#pragma unroll
        for (int m = 0; m < 4; m++) sB[t + 256 * m] = gB[t + 256 * m];
        if (t < 32) sF[t] = g_f2p[(size_t)(jStart / 16) * 4 + t];
    }

    // per-lane row constants (log2 space)
    float f1L0 = g_f1L[mrow + fr];
    float f1L1 = g_f1L[mrow + fr + 8];
    float mL   = g_maxf2L;
    float y0 = f1L0 + mL, y1 = f1L1 + mL;
    float ci0 = fmaxf(y0, 0.01f * y0);    // row max of lrelu (exact; lrelu monotone)
    float ci1 = fmaxf(y1, 0.01f * y1);

    const int4* pr0 = reinterpret_cast<const int4*>(adj + (size_t)(mrow + fr) * N_ + jStart) + fc;
    const int4* pr1 = reinterpret_cast<const int4*>(adj + (size_t)(mrow + fr + 8) * N_ + jStart) + fc;

    float accv[8][4];
#pragma unroll
    for (int q = 0; q < 8; q++)
#pragma unroll
        for (int g = 0; g < 4; g++) accv[q][g] = 0.f;
    float accs[4] = {0.f, 0.f, 0.f, 0.f};

    const uint32_t bone = (fr == 0) ? 0x3C003C00u : 0u;   // ones-column B tile

    // adj for chunk 0 / kk 0
    int4 avA0 = __ldcs(pr0), avA1 = __ldcs(pr1);
    __syncthreads();

    // e = 2^(lrelu(f1+f2) - ci) in (0,1]; masked slots zeroed by half2 AND
    // (adj is exactly {0,1}: msk = x*0xFFFF + y*0xFFFF0000)
#define GEN_A(AREG, AVA, AVB, FV)                                                 \
    do {                                                                          \
        float e00, e01, e02, e03, e10, e11, e12, e13;                             \
        { float y = f1L0 + (FV).x; e00 = ex2f(fmaxf(y - ci0, fmaf(y, 0.01f, -ci0))); } \
        { float y = f1L0 + (FV).y; e01 = ex2f(fmaxf(y - ci0, fmaf(y, 0.01f, -ci0))); } \
        { float y = f1L0 + (FV).z; e02 = ex2f(fmaxf(y - ci0, fmaf(y, 0.01f, -ci0))); } \
        { float y = f1L0 + (FV).w; e03 = ex2f(fmaxf(y - ci0, fmaf(y, 0.01f, -ci0))); } \
        { float y = f1L1 + (FV).x; e10 = ex2f(fmaxf(y - ci1, fmaf(y, 0.01f, -ci1))); } \
        { float y = f1L1 + (FV).y; e11 = ex2f(fmaxf(y - ci1, fmaf(y, 0.01f, -ci1))); } \
        { float y = f1L1 + (FV).z; e12 = ex2f(fmaxf(y - ci1, fmaf(y, 0.01f, -ci1))); } \
        { float y = f1L1 + (FV).w; e13 = ex2f(fmaxf(y - ci1, fmaf(y, 0.01f, -ci1))); } \
        __half2 h0 = __floats2half2_rn(e00, e01);                                 \
        __half2 h1 = __floats2half2_rn(e10, e11);                                 \
        __half2 h2 = __floats2half2_rn(e02, e03);                                 \
        __half2 h3 = __floats2half2_rn(e12, e13);                                 \
        uint32_t mA0 = (uint32_t)(AVA).x * 0xFFFFu + (uint32_t)(AVA).y * 0xFFFF0000u; \
        uint32_t mA1 = (uint32_t)(AVA).z * 0xFFFFu + (uint32_t)(AVA).w * 0xFFFF0000u; \
        uint32_t mB0 = (uint32_t)(AVB).x * 0xFFFFu + (uint32_t)(AVB).y * 0xFFFF0000u; \
        uint32_t mB1 = (uint32_t)(AVB).z * 0xFFFFu + (uint32_t)(AVB).w * 0xFFFF0000u; \
        (AREG)[0] = *reinterpret_cast<uint32_t*>(&h0) & mA0;                      \
        (AREG)[1] = *reinterpret_cast<uint32_t*>(&h1) & mB0;                      \
        (AREG)[2] = *reinterpret_cast<uint32_t*>(&h2) & mA1;                      \
        (AREG)[3] = *reinterpret_cast<uint32_t*>(&h3) & mB1;                      \
    } while (0)

#pragma unroll
    for (int ch = 0; ch < CH; ch++) {
        // prefetch kk1 adj
        int4 avB0 = __ldcs(pr0 + 4), avB1 = __ldcs(pr1 + 4);

        // ---- kk = 0 ----
        {
            uint4 bq[4];
#pragma unroll
            for (int qq = 0; qq < 4; qq++) bq[qq] = sB[ch * 256 + qq * 32 + lane];
            float4 fv = sF[ch * 8 + fc];
            uint32_t a[4];
            GEN_A(a, avA0, avA1, fv);
#pragma unroll
            for (int qq = 0; qq < 4; qq++) {
                mma16(accv[qq],     a, bq[qq].x, bq[qq].y);
                mma16(accv[qq + 4], a, bq[qq].z, bq[qq].w);
            }
            mma16(accs, a, bone, bone);
        }

        // prefetch next chunk's kk0 adj
        if (ch + 1 < CH) { avA0 = __ldcs(pr0 + 8); avA1 = __ldcs(pr1 + 8); }

        // ---- kk = 1 ----
        {
            uint4 bq[4];
#pragma unroll
            for (int qq = 0; qq < 4; qq++) bq[qq] = sB[ch * 256 + 128 + qq * 32 + lane];
            float4 fv = sF[ch * 8 + 4 + fc];
            uint32_t a[4];
            GEN_A(a, avB0, avB1, fv);
#pragma unroll
            for (int qq = 0; qq < 4; qq++) {
                mma16(accv[qq],     a, bq[qq].x, bq[qq].y);
                mma16(accv[qq + 4], a, bq[qq].z, bq[qq].w);
            }
            mma16(accs, a, bone, bone);
        }

        pr0 += 8; pr1 += 8;
    }
#undef GEN_A

    // epilogue: numerators
#pragma unroll
    for (int q = 0; q < 8; q++) {
        int col = q * 8 + 2 * fc;
        red2(&g_V[(mrow + fr) * OUTD + col],     accv[q][0], accv[q][1]);
        red2(&g_V[(mrow + fr + 8) * OUTD + col], accv[q][2], accv[q][3]);
    }
    // denominators
    if (fc == 0) {
        red1(&g_S[mrow + fr],     accs[0]);
        red1(&g_S[mrow + fr + 8], accs[2]);
    }
}

// ---------------- launch 5: normalize + scalar outputs ----------------
__global__ void k_fin(float* __restrict__ out) {
    int gid = blockIdx.x * blockDim.x + threadIdx.x;
    out[gid] = g_V[gid] / g_S[gid >> 6];
    if (gid < 3) {
        float x;
        if (gid == 0)      x = g_f1[1] + g_f2[2];   // face_Rhand = e[1,2]
        else if (gid == 1) x = g_f1[1] + g_f2[3];   // face_Lhand = e[1,3]
        else               x = g_f1[3] + g_f2[2];   // Rhand_Lhand = e[3,2]
        out[N_ * OUTD + gid] = fmaxf(x, 0.01f * x);
    }
}

// ---------------- launch ----------------
extern "C" void kernel_launch(void* const* d_in, const int* in_sizes, int n_in,
                              void* d_out, int out_size) {
    const float* input = (const float*)d_in[0];
    const int*   adj   = (const int*)  d_in[1];
    const float* W     = (const float*)d_in[2];
    const float* a     = (const float*)d_in[3];
    float*       out   = (float*)d_out;
    (void)in_sizes; (void)n_in; (void)out_size;

    const int smem_h = (64 * 260 + 256 * 64) * 4;   // 132096 B
    cudaFuncSetAttribute(k_h, cudaFuncAttributeMaxDynamicSharedMemorySize, smem_h);

    k_zero<<<520, 256>>>();
    k_h   <<<128, 256, smem_h>>>(input, W, a);
    k_prep<<<128, 256>>>();
    k_attn<<<dim3(NS, N_ / 128), 256>>>(adj);   // 4th launch -> profiled
    k_fin <<<2048, 256>>>(out);
}

// round 12
// speedup vs baseline: 1.1208x; 1.1208x over previous
#include <cuda_runtime.h>
#include <cuda_fp16.h>
#include <cstdint>
#include <cstddef>

#define N_    8192
#define IND   256
#define OUTD  64
#define NS    32                 // j splits -> 2048 attention blocks
#define JSPL  (N_ / NS)          // 256 j per block
#define CH    (JSPL / 32)        // 8 chunks
#define L2E   1.4426950408889634f

// ---------------- device scratch (no runtime allocation allowed) ----------------
__device__ __align__(16) float  g_h  [N_ * OUTD];
__device__ __align__(16) uint4  g_hB4[(N_ / 16) * 128];      // B fragments uint4-paired, 1MB
__device__ __align__(16) float4 g_f2p[(N_ / 16) * 4];        // permuted f2*log2e
__device__ __align__(16) float  g_f1 [N_];
__device__ __align__(16) float  g_f1L[N_];                   // f1*log2e
__device__ __align__(16) float  g_f2 [N_];
__device__ __align__(16) float  g_V  [N_ * OUTD];
__device__ __align__(16) float  g_S  [N_];
__device__ uint32_t g_maxkey;
__device__ float    g_maxf2L;

typedef unsigned long long ull;

// ---------------- helpers ----------------
__device__ __forceinline__ ull pk2(float x) {
    ull u; asm("mov.b64 %0, {%1, %1};" : "=l"(u) : "r"(__float_as_uint(x))); return u;
}
__device__ __forceinline__ void ffma2(ull& d, ull a, ull b) {
    asm("fma.rn.f32x2 %0, %1, %2, %0;" : "+l"(d) : "l"(a), "l"(b));
}
__device__ __forceinline__ float2 upk(ull u) {
    float2 f; asm("mov.b64 {%0, %1}, %2;" : "=f"(f.x), "=f"(f.y) : "l"(u)); return f;
}
__device__ __forceinline__ void red2(float* p, float a, float b) {
    asm volatile("red.global.add.v2.f32 [%0], {%1, %2};"
                 :: "l"(p), "f"(a), "f"(b) : "memory");
}
__device__ __forceinline__ void red1(float* p, float a) {
    asm volatile("red.global.add.f32 [%0], %1;" :: "l"(p), "f"(a) : "memory");
}
__device__ __forceinline__ void redmax(uint32_t* p, uint32_t v) {
    asm volatile("red.global.max.u32 [%0], %1;" :: "l"(p), "r"(v) : "memory");
}
__device__ __forceinline__ float ex2f(float x) {
    float r; asm("ex2.approx.f32 %0, %1;" : "=f"(r) : "f"(x)); return r;
}
__device__ __forceinline__ void mma16(float* d, const uint32_t* a, uint32_t b0, uint32_t b1) {
    asm volatile("mma.sync.aligned.m16n8k16.row.col.f32.f16.f16.f32 "
                 "{%0,%1,%2,%3}, {%4,%5,%6,%7}, {%8,%9}, {%0,%1,%2,%3};"
                 : "+f"(d[0]), "+f"(d[1]), "+f"(d[2]), "+f"(d[3])
                 : "r"(a[0]), "r"(a[1]), "r"(a[2]), "r"(a[3]), "r"(b0), "r"(b1));
}

// ---------------- launch 1: zero V/S + maxkey reset ----------------
__global__ void k_zero() {
    int i = blockIdx.x * blockDim.x + threadIdx.x;
    if (i == 0) g_maxkey = 0u;
    float4 z = make_float4(0.f, 0.f, 0.f, 0.f);
    if (i < (N_ * OUTD) / 4) reinterpret_cast<float4*>(g_V)[i] = z;
    else                     reinterpret_cast<float4*>(g_S)[i - (N_ * OUTD) / 4] = z;
}

// ---------------- launch 2: h = input @ W (f32x2) + fused f1/f2 + red.max ----------------
__global__ void __launch_bounds__(256) k_h(const float* __restrict__ input,
                                           const float* __restrict__ W,
                                           const float* __restrict__ a) {
    extern __shared__ float sm[];
    float* in_s = sm;
    float* W_s  = sm + 64 * 260;
    int t = threadIdx.x;
    int rowBase = blockIdx.x * 64;

#pragma unroll
    for (int m = 0; m < 16; m++) {
        int idx4 = t + 256 * m;
        *reinterpret_cast<float4*>(&W_s[4 * idx4]) =
            *reinterpret_cast<const float4*>(&W[4 * idx4]);
    }
#pragma unroll
    for (int m = 0; m < 16; m++) {
        int idx4 = t + 256 * m;
        int r = idx4 >> 6, k4 = (idx4 & 63) * 4;
        *reinterpret_cast<float4*>(&in_s[r * 260 + k4]) =
            *reinterpret_cast<const float4*>(&input[(size_t)(rowBase + r) * IND + k4]);
    }
    __syncthreads();

    int ty = t >> 3, tx = t & 7;
    ull acc[2][4];
#pragma unroll
    for (int r = 0; r < 2; r++)
#pragma unroll
        for (int g = 0; g < 4; g++) acc[r][g] = 0ull;

#pragma unroll 8
    for (int k = 0; k < IND; k++) {
        ulonglong2 wa = *reinterpret_cast<const ulonglong2*>(&W_s[k * 64 + 4 * tx]);
        ulonglong2 wb = *reinterpret_cast<const ulonglong2*>(&W_s[k * 64 + 32 + 4 * tx]);
#pragma unroll
        for (int r = 0; r < 2; r++) {
            ull iv = pk2(in_s[(2 * ty + r) * 260 + k]);
            ffma2(acc[r][0], iv, wa.x); ffma2(acc[r][1], iv, wa.y);
            ffma2(acc[r][2], iv, wb.x); ffma2(acc[r][3], iv, wb.y);
        }
    }

    float4 A1a = *reinterpret_cast<const float4*>(&a[4 * tx]);
    float4 A1b = *reinterpret_cast<const float4*>(&a[32 + 4 * tx]);
    float4 A2a = *reinterpret_cast<const float4*>(&a[OUTD + 4 * tx]);
    float4 A2b = *reinterpret_cast<const float4*>(&a[OUTD + 32 + 4 * tx]);

#pragma unroll
    for (int r = 0; r < 2; r++) {
        int row = rowBase + 2 * ty + r;
        float2 p0 = upk(acc[r][0]), p1 = upk(acc[r][1]);
        float2 p2 = upk(acc[r][2]), p3 = upk(acc[r][3]);
        *reinterpret_cast<float4*>(&g_h[row * OUTD + 4 * tx]) = make_float4(p0.x, p0.y, p1.x, p1.y);
        *reinterpret_cast<float4*>(&g_h[row * OUTD + 32 + 4 * tx]) = make_float4(p2.x, p2.y, p3.x, p3.y);

        float s1 = p0.x * A1a.x + p0.y * A1a.y + p1.x * A1a.z + p1.y * A1a.w
                 + p2.x * A1b.x + p2.y * A1b.y + p3.x * A1b.z + p3.y * A1b.w;
        float s2 = p0.x * A2a.x + p0.y * A2a.y + p1.x * A2a.z + p1.y * A2a.w
                 + p2.x * A2b.x + p2.y * A2b.y + p3.x * A2b.z + p3.y * A2b.w;
#pragma unroll
        for (int off = 1; off < 8; off <<= 1) {
            s1 += __shfl_xor_sync(0xFFFFFFFFu, s1, off);
            s2 += __shfl_xor_sync(0xFFFFFFFFu, s2, off);
        }
        if (tx == 0) {
            g_f1[row]  = s1;
            g_f1L[row] = s1 * L2E;
            g_f2[row]  = s2;
            uint32_t u = __float_as_uint(s2);
            uint32_t key = u ^ (uint32_t)(((int)u >> 31) | 0x80000000);
            redmax(&g_maxkey, key);
        }
    }
}

// ---------------- launch 3: pack permuted B fragments + f2p + decode max ----------------
__global__ void __launch_bounds__(256) k_prep() {
    __shared__ float tile[64][65];
    int t = threadIdx.x, b = blockIdx.x;
    int jBase = b * 64;

    if (b == 0 && t == 0) {
        uint32_t k = g_maxkey;
        uint32_t u = (k & 0x80000000u) ? (k ^ 0x80000000u) : ~k;
        g_maxf2L = __uint_as_float(u) * L2E;
    }

    if (t < 16) {
        int j16r = t >> 2, fc = t & 3;
        int j = jBase + j16r * 16 + 4 * fc;
        float4 v;
        v.x = g_f2[j]     * L2E;
        v.y = g_f2[j + 1] * L2E;
        v.z = g_f2[j + 2] * L2E;
        v.w = g_f2[j + 3] * L2E;
        g_f2p[(jBase / 16 + j16r) * 4 + fc] = v;
    }

#pragma unroll
    for (int m = 0; m < 4; m++) {
        int idx = t + 256 * m;
        int j = idx >> 4, c4 = (idx & 15) * 4;
        float4 v = *reinterpret_cast<const float4*>(&g_h[(size_t)(jBase + j) * OUTD + c4]);
        tile[j][c4] = v.x; tile[j][c4 + 1] = v.y; tile[j][c4 + 2] = v.z; tile[j][c4 + 3] = v.w;
    }
    __syncthreads();

#pragma unroll
    for (int m = 0; m < 2; m++) {
        int idx = t + 256 * m;            // 0..511 = j16r(4) x qq(4) x lane(32)
        int j16r = idx >> 7;
        int qq   = (idx >> 5) & 3;
        int lane = idx & 31;
        int fr = lane >> 2, fc = lane & 3;
        int j0 = j16r * 16 + 4 * fc;
        int n1 = qq * 8 + fr;
        int n2 = (qq + 4) * 8 + fr;
        __half2 lo1 = __floats2half2_rn(tile[j0][n1],     tile[j0 + 1][n1]);
        __half2 hi1 = __floats2half2_rn(tile[j0 + 2][n1], tile[j0 + 3][n1]);
        __half2 lo2 = __floats2half2_rn(tile[j0][n2],     tile[j0 + 1][n2]);
        __half2 hi2 = __floats2half2_rn(tile[j0 + 2][n2], tile[j0 + 3][n2]);
        uint4 pkt;
        pkt.x = *reinterpret_cast<uint32_t*>(&lo1);
        pkt.y = *reinterpret_cast<uint32_t*>(&hi1);
        pkt.z = *reinterpret_cast<uint32_t*>(&lo2);
        pkt.w = *reinterpret_cast<uint32_t*>(&hi2);
        g_hB4[((jBase / 16 + j16r) * 4 + qq) * 32 + lane] = pkt;
    }
}

// ---------------- launch 4 (PROFILED): smem-B register-fragment attention ----------------
// R9 geometry (NS=32, 32KB sB, 3 blocks/SM) + IMAD/LOP mask GEN (no I2F).
__global__ void __launch_bounds__(256, 3) k_attn(const int* __restrict__ adj) {
    __shared__ uint4  sB[2048];   // 32KB B fragments for this block's 256 j
    __shared__ float4 sF[64];     // 1KB  f2p

    int t = threadIdx.x;
    int wid = t >> 5, lane = t & 31;
    int fr = lane >> 2, fc = lane & 3;
    int mrow   = blockIdx.y * 128 + wid * 16;
    int jStart = blockIdx.x * JSPL;

    // stage B + f2 tiles (one-time, L2-resident source)
    {
        const uint4* gB = g_hB4 + (size_t)(jStart / 16) * 128;
#pragma unroll
        for (int m = 0; m < 8; m++) sB[t + 256 * m] = gB[t + 256 * m];
        if (t < 64) sF[t] = g_f2p[(size_t)(jStart / 16) * 4 + t];
    }

    // per-lane row constants (log2 space)
    float f1L0 = g_f1L[mrow + fr];
    float f1L1 = g_f1L[mrow + fr + 8];
    float mL   = g_maxf2L;
    float y0 = f1L0 + mL, y1 = f1L1 + mL;
    float ci0 = fmaxf(y0, 0.01f * y0);    // row max of lrelu (exact; lrelu monotone)
    float ci1 = fmaxf(y1, 0.01f * y1);

    const int4* pr0 = reinterpret_cast<const int4*>(adj + (size_t)(mrow + fr) * N_ + jStart) + fc;
    const int4* pr1 = reinterpret_cast<const int4*>(adj + (size_t)(mrow + fr + 8) * N_ + jStart) + fc;

    float accv[8][4];
#pragma unroll
    for (int q = 0; q < 8; q++)
#pragma unroll
        for (int g = 0; g < 4; g++) accv[q][g] = 0.f;
    float accs[4] = {0.f, 0.f, 0.f, 0.f};

    const uint32_t bone = (fr == 0) ? 0x3C003C00u : 0u;   // ones-column B tile

    // adj for chunk 0 / kk 0
    int4 avA0 = __ldcs(pr0), avA1 = __ldcs(pr1);
    __syncthreads();

    // e = 2^(lrelu(f1+f2) - ci) in (0,1]; masked slots zeroed by half2 AND
    // (adj is exactly {0,1}: msk = x*0xFFFF + y*0xFFFF0000)
#define GEN_A(AREG, AVA, AVB, FV)                                                 \
    do {                                                                          \
        float e00, e01, e02, e03, e10, e11, e12, e13;                             \
        { float y = f1L0 + (FV).x; e00 = ex2f(fmaxf(y - ci0, fmaf(y, 0.01f, -ci0))); } \
        { float y = f1L0 + (FV).y; e01 = ex2f(fmaxf(y - ci0, fmaf(y, 0.01f, -ci0))); } \
        { float y = f1L0 + (FV).z; e02 = ex2f(fmaxf(y - ci0, fmaf(y, 0.01f, -ci0))); } \
        { float y = f1L0 + (FV).w; e03 = ex2f(fmaxf(y - ci0, fmaf(y, 0.01f, -ci0))); } \
        { float y = f1L1 + (FV).x; e10 = ex2f(fmaxf(y - ci1, fmaf(y, 0.01f, -ci1))); } \
        { float y = f1L1 + (FV).y; e11 = ex2f(fmaxf(y - ci1, fmaf(y, 0.01f, -ci1))); } \
        { float y = f1L1 + (FV).z; e12 = ex2f(fmaxf(y - ci1, fmaf(y, 0.01f, -ci1))); } \
        { float y = f1L1 + (FV).w; e13 = ex2f(fmaxf(y - ci1, fmaf(y, 0.01f, -ci1))); } \
        __half2 h0 = __floats2half2_rn(e00, e01);                                 \
        __half2 h1 = __floats2half2_rn(e10, e11);                                 \
        __half2 h2 = __floats2half2_rn(e02, e03);                                 \
        __half2 h3 = __floats2half2_rn(e12, e13);                                 \
        uint32_t mA0 = (uint32_t)(AVA).x * 0xFFFFu + (uint32_t)(AVA).y * 0xFFFF0000u; \
        uint32_t mA1 = (uint32_t)(AVA).z * 0xFFFFu + (uint32_t)(AVA).w * 0xFFFF0000u; \
        uint32_t mB0 = (uint32_t)(AVB).x * 0xFFFFu + (uint32_t)(AVB).y * 0xFFFF0000u; \
        uint32_t mB1 = (uint32_t)(AVB).z * 0xFFFFu + (uint32_t)(AVB).w * 0xFFFF0000u; \
        (AREG)[0] = *reinterpret_cast<uint32_t*>(&h0) & mA0;                      \
        (AREG)[1] = *reinterpret_cast<uint32_t*>(&h1) & mB0;                      \
        (AREG)[2] = *reinterpret_cast<uint32_t*>(&h2) & mA1;                      \
        (AREG)[3] = *reinterpret_cast<uint32_t*>(&h3) & mB1;                      \
    } while (0)

#pragma unroll 2
    for (int ch = 0; ch < CH; ch++) {
        // prefetch kk1 adj (used ~60 instrs later)
        int4 avB0 = __ldcs(pr0 + 4), avB1 = __ldcs(pr1 + 4);

        // ---- kk = 0 ----
        {
            uint4 bq[4];
#pragma unroll
            for (int qq = 0; qq < 4; qq++) bq[qq] = sB[ch * 256 + qq * 32 + lane];
            float4 fv = sF[ch * 8 + fc];
            uint32_t a[4];
            GEN_A(a, avA0, avA1, fv);
#pragma unroll
            for (int qq = 0; qq < 4; qq++) {
                mma16(accv[qq],     a, bq[qq].x, bq[qq].y);
                mma16(accv[qq + 4], a, bq[qq].z, bq[qq].w);
            }
            mma16(accs, a, bone, bone);
        }

        // prefetch next chunk's kk0 adj
        if (ch + 1 < CH) { avA0 = __ldcs(pr0 + 8); avA1 = __ldcs(pr1 + 8); }

        // ---- kk = 1 ----
        {
            uint4 bq[4];
#pragma unroll
            for (int qq = 0; qq < 4; qq++) bq[qq] = sB[ch * 256 + 128 + qq * 32 + lane];
            float4 fv = sF[ch * 8 + 4 + fc];
            uint32_t a[4];
            GEN_A(a, avB0, avB1, fv);
#pragma unroll
            for (int qq = 0; qq < 4; qq++) {
                mma16(accv[qq],     a, bq[qq].x, bq[qq].y);
                mma16(accv[qq + 4], a, bq[qq].z, bq[qq].w);
            }
            mma16(accs, a, bone, bone);
        }

        pr0 += 8; pr1 += 8;
    }
#undef GEN_A

    // epilogue: numerators
#pragma unroll
    for (int q = 0; q < 8; q++) {
        int col = q * 8 + 2 * fc;
        red2(&g_V[(mrow + fr) * OUTD + col],     accv[q][0], accv[q][1]);
        red2(&g_V[(mrow + fr + 8) * OUTD + col], accv[q][2], accv[q][3]);
    }
    // denominators
    if (fc == 0) {
        red1(&g_S[mrow + fr],     accs[0]);
        red1(&g_S[mrow + fr + 8], accs[2]);
    }
}

// ---------------- launch 5: normalize + scalar outputs ----------------
__global__ void k_fin(float* __restrict__ out) {
    int gid = blockIdx.x * blockDim.x + threadIdx.x;
    out[gid] = g_V[gid] / g_S[gid >> 6];
    if (gid < 3) {
        float x;
        if (gid == 0)      x = g_f1[1] + g_f2[2];   // face_Rhand = e[1,2]
        else if (gid == 1) x = g_f1[1] + g_f2[3];   // face_Lhand = e[1,3]
        else               x = g_f1[3] + g_f2[2];   // Rhand_Lhand = e[3,2]
        out[N_ * OUTD + gid] = fmaxf(x, 0.01f * x);
    }
}

// ---------------- launch ----------------
extern "C" void kernel_launch(void* const* d_in, const int* in_sizes, int n_in,
                              void* d_out, int out_size) {
    const float* input = (const float*)d_in[0];
    const int*   adj   = (const int*)  d_in[1];
    const float* W     = (const float*)d_in[2];
    const float* a     = (const float*)d_in[3];
    float*       out   = (float*)d_out;
    (void)in_sizes; (void)n_in; (void)out_size;

    const int smem_h = (64 * 260 + 256 * 64) * 4;   // 132096 B
    cudaFuncSetAttribute(k_h, cudaFuncAttributeMaxDynamicSharedMemorySize, smem_h);

    k_zero<<<520, 256>>>();
    k_h   <<<128, 256, smem_h>>>(input, W, a);
    k_prep<<<128, 256>>>();
    k_attn<<<dim3(NS, N_ / 128), 256>>>(adj);   // 4th launch -> profiled
    k_fin <<<2048, 256>>>(out);
}

// round 13
// speedup vs baseline: 1.1612x; 1.0360x over previous
#include <cuda_runtime.h>
#include <cuda_fp16.h>
#include <cstdint>
#include <cstddef>

#define N_    8192
#define IND   256
#define OUTD  64
#define NS    32                 // j splits -> 2048 attention blocks
#define JSPL  (N_ / NS)          // 256 j per block
#define CH    (JSPL / 32)        // 8 chunks
#define L2E   1.4426950408889634f

// ---------------- device scratch (no runtime allocation allowed) ----------------
__device__ __align__(16) uint4  g_hB4[(N_ / 16) * 128];      // B fragments uint4-paired, 1MB
__device__ __align__(16) float4 g_f2p[(N_ / 16) * 4];        // permuted f2*log2e
__device__ __align__(16) float  g_f1 [N_];
__device__ __align__(16) float  g_f1L[N_];                   // f1*log2e
__device__ __align__(16) float  g_f2 [N_];
__device__ __align__(16) float  g_V  [N_ * OUTD];
__device__ __align__(16) float  g_S  [N_];
__device__ uint32_t g_maxkey;

typedef unsigned long long ull;

// ---------------- helpers ----------------
__device__ __forceinline__ ull pk2(float x) {
    ull u; asm("mov.b64 %0, {%1, %1};" : "=l"(u) : "r"(__float_as_uint(x))); return u;
}
__device__ __forceinline__ void ffma2(ull& d, ull a, ull b) {
    asm("fma.rn.f32x2 %0, %1, %2, %0;" : "+l"(d) : "l"(a), "l"(b));
}
__device__ __forceinline__ float2 upk(ull u) {
    float2 f; asm("mov.b64 {%0, %1}, %2;" : "=f"(f.x), "=f"(f.y) : "l"(u)); return f;
}
__device__ __forceinline__ void red2(float* p, float a, float b) {
    asm volatile("red.global.add.v2.f32 [%0], {%1, %2};"
                 :: "l"(p), "f"(a), "f"(b) : "memory");
}
__device__ __forceinline__ void red1(float* p, float a) {
    asm volatile("red.global.add.f32 [%0], %1;" :: "l"(p), "f"(a) : "memory");
}
__device__ __forceinline__ void redmax(uint32_t* p, uint32_t v) {
    asm volatile("red.global.max.u32 [%0], %1;" :: "l"(p), "r"(v) : "memory");
}
__device__ __forceinline__ float ex2f(float x) {
    float r; asm("ex2.approx.f32 %0, %1;" : "=f"(r) : "f"(x)); return r;
}
__device__ __forceinline__ void mma16(float* d, const uint32_t* a, uint32_t b0, uint32_t b1) {
    asm volatile("mma.sync.aligned.m16n8k16.row.col.f32.f16.f16.f32 "
                 "{%0,%1,%2,%3}, {%4,%5,%6,%7}, {%8,%9}, {%0,%1,%2,%3};"
                 : "+f"(d[0]), "+f"(d[1]), "+f"(d[2]), "+f"(d[3])
                 : "r"(a[0]), "r"(a[1]), "r"(a[2]), "r"(a[3]), "r"(b0), "r"(b1));
}

// ---------------- launch 1: zero V/S + maxkey reset ----------------
__global__ void k_zero() {
    int i = blockIdx.x * blockDim.x + threadIdx.x;
    if (i == 0) g_maxkey = 0u;
    float4 z = make_float4(0.f, 0.f, 0.f, 0.f);
    if (i < (N_ * OUTD) / 4) reinterpret_cast<float4*>(g_V)[i] = z;
    else                     reinterpret_cast<float4*>(g_S)[i - (N_ * OUTD) / 4] = z;
}

// ---------------- launch 2: h = input@W + f1/f2 + red.max + B-fragment pack ----------------
// Fuses the old k_prep: block b computes h for rows [64b, 64b+64) AND packs the
// permuted fp16 B fragments + f2p for those same 64 j directly from registers/smem.
__global__ void __launch_bounds__(256) k_h(const float* __restrict__ input,
                                           const float* __restrict__ W,
                                           const float* __restrict__ a) {
    extern __shared__ float sm[];
    float* in_s = sm;               // [64][260] during GEMM; reused as tile after
    float* W_s  = sm + 64 * 260;    // [256][64]
    int t = threadIdx.x;
    int rowBase = blockIdx.x * 64;

#pragma unroll
    for (int m = 0; m < 16; m++) {
        int idx4 = t + 256 * m;
        *reinterpret_cast<float4*>(&W_s[4 * idx4]) =
            *reinterpret_cast<const float4*>(&W[4 * idx4]);
    }
#pragma unroll
    for (int m = 0; m < 16; m++) {
        int idx4 = t + 256 * m;
        int r = idx4 >> 6, k4 = (idx4 & 63) * 4;
        *reinterpret_cast<float4*>(&in_s[r * 260 + k4]) =
            *reinterpret_cast<const float4*>(&input[(size_t)(rowBase + r) * IND + k4]);
    }
    __syncthreads();

    int ty = t >> 3, tx = t & 7;
    ull acc[2][4];
#pragma unroll
    for (int r = 0; r < 2; r++)
#pragma unroll
        for (int g = 0; g < 4; g++) acc[r][g] = 0ull;

#pragma unroll 8
    for (int k = 0; k < IND; k++) {
        ulonglong2 wa = *reinterpret_cast<const ulonglong2*>(&W_s[k * 64 + 4 * tx]);
        ulonglong2 wb = *reinterpret_cast<const ulonglong2*>(&W_s[k * 64 + 32 + 4 * tx]);
#pragma unroll
        for (int r = 0; r < 2; r++) {
            ull iv = pk2(in_s[(2 * ty + r) * 260 + k]);
            ffma2(acc[r][0], iv, wa.x); ffma2(acc[r][1], iv, wa.y);
            ffma2(acc[r][2], iv, wb.x); ffma2(acc[r][3], iv, wb.y);
        }
    }

    float4 A1a = *reinterpret_cast<const float4*>(&a[4 * tx]);
    float4 A1b = *reinterpret_cast<const float4*>(&a[32 + 4 * tx]);
    float4 A2a = *reinterpret_cast<const float4*>(&a[OUTD + 4 * tx]);
    float4 A2b = *reinterpret_cast<const float4*>(&a[OUTD + 32 + 4 * tx]);

    // reuse smem: tile[64][65] for h transpose, f2s[64] for scaled f2
    float* tile = sm;               // 64*65 = 4160 floats
    float* f2s  = sm + 64 * 65;     // 64 floats

    __syncthreads();   // all reads of in_s/W_s complete before overwrite

#pragma unroll
    for (int r = 0; r < 2; r++) {
        int lrow = 2 * ty + r;                 // local row 0..63
        int row  = rowBase + lrow;
        float2 p0 = upk(acc[r][0]), p1 = upk(acc[r][1]);
        float2 p2 = upk(acc[r][2]), p3 = upk(acc[r][3]);

        float* tr = &tile[lrow * 65];
        tr[4 * tx]     = p0.x; tr[4 * tx + 1] = p0.y;
        tr[4 * tx + 2] = p1.x; tr[4 * tx + 3] = p1.y;
        tr[32 + 4 * tx]     = p2.x; tr[32 + 4 * tx + 1] = p2.y;
        tr[32 + 4 * tx + 2] = p3.x; tr[32 + 4 * tx + 3] = p3.y;

        float s1 = p0.x * A1a.x + p0.y * A1a.y + p1.x * A1a.z + p1.y * A1a.w
                 + p2.x * A1b.x + p2.y * A1b.y + p3.x * A1b.z + p3.y * A1b.w;
        float s2 = p0.x * A2a.x + p0.y * A2a.y + p1.x * A2a.z + p1.y * A2a.w
                 + p2.x * A2b.x + p2.y * A2b.y + p3.x * A2b.z + p3.y * A2b.w;
#pragma unroll
        for (int off = 1; off < 8; off <<= 1) {
            s1 += __shfl_xor_sync(0xFFFFFFFFu, s1, off);
            s2 += __shfl_xor_sync(0xFFFFFFFFu, s2, off);
        }
        if (tx == 0) {
            g_f1[row]  = s1;
            g_f1L[row] = s1 * L2E;
            g_f2[row]  = s2;
            f2s[lrow]  = s2 * L2E;
            uint32_t u = __float_as_uint(s2);
            uint32_t key = u ^ (uint32_t)(((int)u >> 31) | 0x80000000);
            redmax(&g_maxkey, key);
        }
    }
    __syncthreads();

    int jBase = rowBase;   // these 64 rows are j-rows for the pack

    // f2p (permuted): g_f2p[j16*4 + fc] = {f2L[j16*16+4fc+0..3]}
    if (t < 16) {
        int j16r = t >> 2, fc = t & 3;
        int j = j16r * 16 + 4 * fc;
        float4 v;
        v.x = f2s[j]; v.y = f2s[j + 1]; v.z = f2s[j + 2]; v.w = f2s[j + 3];
        g_f2p[(jBase / 16 + j16r) * 4 + fc] = v;
    }

    // pack B fragments (permuted, uint4 pairs q/q+4)
#pragma unroll
    for (int m = 0; m < 2; m++) {
        int idx = t + 256 * m;            // 0..511 = j16r(4) x qq(4) x lane(32)
        int j16r = idx >> 7;
        int qq   = (idx >> 5) & 3;
        int lane = idx & 31;
        int fr = lane >> 2, fc = lane & 3;
        int j0 = j16r * 16 + 4 * fc;
        int n1 = qq * 8 + fr;
        int n2 = (qq + 4) * 8 + fr;
        __half2 lo1 = __floats2half2_rn(tile[j0 * 65 + n1],       tile[(j0 + 1) * 65 + n1]);
        __half2 hi1 = __floats2half2_rn(tile[(j0 + 2) * 65 + n1], tile[(j0 + 3) * 65 + n1]);
        __half2 lo2 = __floats2half2_rn(tile[j0 * 65 + n2],       tile[(j0 + 1) * 65 + n2]);
        __half2 hi2 = __floats2half2_rn(tile[(j0 + 2) * 65 + n2], tile[(j0 + 3) * 65 + n2]);
        uint4 pkt;
        pkt.x = *reinterpret_cast<uint32_t*>(&lo1);
        pkt.y = *reinterpret_cast<uint32_t*>(&hi1);
        pkt.z = *reinterpret_cast<uint32_t*>(&lo2);
        pkt.w = *reinterpret_cast<uint32_t*>(&hi2);
        g_hB4[((jBase / 16 + j16r) * 4 + qq) * 32 + lane] = pkt;
    }
}

// ---------------- launch 3: smem-B register-fragment attention ----------------
// R11 kernel unchanged except maxf2L decoded inline from g_maxkey.
__global__ void __launch_bounds__(256, 3) k_attn(const int* __restrict__ adj) {
    __shared__ uint4  sB[2048];   // 32KB B fragments for this block's 256 j
    __shared__ float4 sF[64];     // 1KB  f2p

    int t = threadIdx.x;
    int wid = t >> 5, lane = t & 31;
    int fr = lane >> 2, fc = lane & 3;
    int mrow   = blockIdx.y * 128 + wid * 16;
    int jStart = blockIdx.x * JSPL;

    // stage B + f2 tiles (one-time, L2-resident source)
    {
        const uint4* gB = g_hB4 + (size_t)(jStart / 16) * 128;
#pragma unroll
        for (int m = 0; m < 8; m++) sB[t + 256 * m] = gB[t + 256 * m];
        if (t < 64) sF[t] = g_f2p[(size_t)(jStart / 16) * 4 + t];
    }

    // decode global max f2 (log2 space) from the order-preserving key
    float mL;
    {
        uint32_t k = g_maxkey;
        uint32_t u = (k & 0x80000000u) ? (k ^ 0x80000000u) : ~k;
        mL = __uint_as_float(u) * L2E;
    }

    // per-lane row constants (log2 space)
    float f1L0 = g_f1L[mrow + fr];
    float f1L1 = g_f1L[mrow + fr + 8];
    float y0 = f1L0 + mL, y1 = f1L1 + mL;
    float ci0 = fmaxf(y0, 0.01f * y0);    // row max of lrelu (exact; lrelu monotone)
    float ci1 = fmaxf(y1, 0.01f * y1);

    const int4* pr0 = reinterpret_cast<const int4*>(adj + (size_t)(mrow + fr) * N_ + jStart) + fc;
    const int4* pr1 = reinterpret_cast<const int4*>(adj + (size_t)(mrow + fr + 8) * N_ + jStart) + fc;

    float accv[8][4];
#pragma unroll
    for (int q = 0; q < 8; q++)
#pragma unroll
        for (int g = 0; g < 4; g++) accv[q][g] = 0.f;
    float accs[4] = {0.f, 0.f, 0.f, 0.f};

    const uint32_t bone = (fr == 0) ? 0x3C003C00u : 0u;   // ones-column B tile

    // adj for chunk 0 / kk 0
    int4 avA0 = __ldcs(pr0), avA1 = __ldcs(pr1);
    __syncthreads();

    // e = 2^(lrelu(f1+f2) - ci) in (0,1]; masked slots zeroed by half2 AND
    // (adj is exactly {0,1}: msk = x*0xFFFF + y*0xFFFF0000)
#define GEN_A(AREG, AVA, AVB, FV)                                                 \
    do {                                                                          \
        float e00, e01, e02, e03, e10, e11, e12, e13;                             \
        { float y = f1L0 + (FV).x; e00 = ex2f(fmaxf(y - ci0, fmaf(y, 0.01f, -ci0))); } \
        { float y = f1L0 + (FV).y; e01 = ex2f(fmaxf(y - ci0, fmaf(y, 0.01f, -ci0))); } \
        { float y = f1L0 + (FV).z; e02 = ex2f(fmaxf(y - ci0, fmaf(y, 0.01f, -ci0))); } \
        { float y = f1L0 + (FV).w; e03 = ex2f(fmaxf(y - ci0, fmaf(y, 0.01f, -ci0))); } \
        { float y = f1L1 + (FV).x; e10 = ex2f(fmaxf(y - ci1, fmaf(y, 0.01f, -ci1))); } \
        { float y = f1L1 + (FV).y; e11 = ex2f(fmaxf(y - ci1, fmaf(y, 0.01f, -ci1))); } \
        { float y = f1L1 + (FV).z; e12 = ex2f(fmaxf(y - ci1, fmaf(y, 0.01f, -ci1))); } \
        { float y = f1L1 + (FV).w; e13 = ex2f(fmaxf(y - ci1, fmaf(y, 0.01f, -ci1))); } \
        __half2 h0 = __floats2half2_rn(e00, e01);                                 \
        __half2 h1 = __floats2half2_rn(e10, e11);                                 \
        __half2 h2 = __floats2half2_rn(e02, e03);                                 \
        __half2 h3 = __floats2half2_rn(e12, e13);                                 \
        uint32_t mA0 = (uint32_t)(AVA).x * 0xFFFFu + (uint32_t)(AVA).y * 0xFFFF0000u; \
        uint32_t mA1 = (uint32_t)(AVA).z * 0xFFFFu + (uint32_t)(AVA).w * 0xFFFF0000u; \
        uint32_t mB0 = (uint32_t)(AVB).x * 0xFFFFu + (uint32_t)(AVB).y * 0xFFFF0000u; \
        uint32_t mB1 = (uint32_t)(AVB).z * 0xFFFFu + (uint32_t)(AVB).w * 0xFFFF0000u; \
        (AREG)[0] = *reinterpret_cast<uint32_t*>(&h0) & mA0;                      \
        (AREG)[1] = *reinterpret_cast<uint32_t*>(&h1) & mB0;                      \
        (AREG)[2] = *reinterpret_cast<uint32_t*>(&h2) & mA1;                      \
        (AREG)[3] = *reinterpret_cast<uint32_t*>(&h3) & mB1;                      \
    } while (0)

#pragma unroll 2
    for (int ch = 0; ch < CH; ch++) {
        // prefetch kk1 adj (used ~60 instrs later)
        int4 avB0 = __ldcs(pr0 + 4), avB1 = __ldcs(pr1 + 4);

        // ---- kk = 0 ----
        {
            uint4 bq[4];
#pragma unroll
            for (int qq = 0; qq < 4; qq++) bq[qq] = sB[ch * 256 + qq * 32 + lane];
            float4 fv = sF[ch * 8 + fc];
            uint32_t a[4];
            GEN_A(a, avA0, avA1, fv);
#pragma unroll
            for (int qq = 0; qq < 4; qq++) {
                mma16(accv[qq],     a, bq[qq].x, bq[qq].y);
                mma16(accv[qq + 4], a, bq[qq].z, bq[qq].w);
            }
            mma16(accs, a, bone, bone);
        }

        // prefetch next chunk's kk0 adj
        if (ch + 1 < CH) { avA0 = __ldcs(pr0 + 8); avA1 = __ldcs(pr1 + 8); }

        // ---- kk = 1 ----
        {
            uint4 bq[4];
#pragma unroll
            for (int qq = 0; qq < 4; qq++) bq[qq] = sB[ch * 256 + 128 + qq * 32 + lane];
            float4 fv = sF[ch * 8 + 4 + fc];
            uint32_t a[4];
            GEN_A(a, avB0, avB1, fv);
#pragma unroll
            for (int qq = 0; qq < 4; qq++) {
                mma16(accv[qq],     a, bq[qq].x, bq[qq].y);
                mma16(accv[qq + 4], a, bq[qq].z, bq[qq].w);
            }
            mma16(accs, a, bone, bone);
        }

        pr0 += 8; pr1 += 8;
    }
#undef GEN_A

    // epilogue: numerators
#pragma unroll
    for (int q = 0; q < 8; q++) {
        int col = q * 8 + 2 * fc;
        red2(&g_V[(mrow + fr) * OUTD + col],     accv[q][0], accv[q][1]);
        red2(&g_V[(mrow + fr + 8) * OUTD + col], accv[q][2], accv[q][3]);
    }
    // denominators
    if (fc == 0) {
        red1(&g_S[mrow + fr],     accs[0]);
        red1(&g_S[mrow + fr + 8], accs[2]);
    }
}

// ---------------- launch 4: normalize (float4) + scalar outputs ----------------
__global__ void __launch_bounds__(256) k_fin(float* __restrict__ out) {
    int gid = blockIdx.x * blockDim.x + threadIdx.x;   // 0..131071 float4s
    float4 v = reinterpret_cast<const float4*>(g_V)[gid];
    float  s = g_S[gid >> 4];                          // 16 float4 per row
    float  inv = 1.0f / s;
    float4 o = make_float4(v.x * inv, v.y * inv, v.z * inv, v.w * inv);
    reinterpret_cast<float4*>(out)[gid] = o;
    if (gid < 3) {
        float x;
        if (gid == 0)      x = g_f1[1] + g_f2[2];   // face_Rhand = e[1,2]
        else if (gid == 1) x = g_f1[1] + g_f2[3];   // face_Lhand = e[1,3]
        else               x = g_f1[3] + g_f2[2];   // Rhand_Lhand = e[3,2]
        out[N_ * OUTD + gid] = fmaxf(x, 0.01f * x);
    }
}

// ---------------- launch ----------------
extern "C" void kernel_launch(void* const* d_in, const int* in_sizes, int n_in,
                              void* d_out, int out_size) {
    const float* input = (const float*)d_in[0];
    const int*   adj   = (const int*)  d_in[1];
    const float* W     = (const float*)d_in[2];
    const float* a     = (const float*)d_in[3];
    float*       out   = (float*)d_out;
    (void)in_sizes; (void)n_in; (void)out_size;

    const int smem_h = (64 * 260 + 256 * 64) * 4;   // 132096 B (pack phase reuses it)
    cudaFuncSetAttribute(k_h, cudaFuncAttributeMaxDynamicSharedMemorySize, smem_h);

    k_zero<<<520, 256>>>();
    k_h   <<<128, 256, smem_h>>>(input, W, a);
    k_attn<<<dim3(NS, N_ / 128), 256>>>(adj);
    k_fin <<<512, 256>>>(out);
}

// round 14
// speedup vs baseline: 1.1877x; 1.0228x over previous
#include <cuda_runtime.h>
#include <cuda_fp16.h>
#include <cstdint>
#include <cstddef>

#define N_    8192
#define IND   256
#define OUTD  64
#define NS    32                 // j splits -> 2048 attention blocks
#define JSPL  (N_ / NS)          // 256 j per block
#define CH    (JSPL / 32)        // 8 chunks
#define L2E   1.4426950408889634f

// ---------------- device scratch (no runtime allocation allowed) ----------------
// NOTE: g_V and g_maxkey are self-restoring: zero-initialized at load, zeroed
// again by k_fin after each use; g_S is zeroed by k_h each call.
__device__ __align__(16) uint4  g_hB4[(N_ / 16) * 128];      // B fragments uint4-paired, 1MB
__device__ __align__(16) float4 g_f2p[(N_ / 16) * 4];        // permuted f2*log2e
__device__ __align__(16) float  g_f1 [N_];
__device__ __align__(16) float  g_f1L[N_];                   // f1*log2e
__device__ __align__(16) float  g_f2 [N_];
__device__ __align__(16) float  g_V  [N_ * OUTD];
__device__ __align__(16) float  g_S  [N_];
__device__ uint32_t g_maxkey;

typedef unsigned long long ull;

// ---------------- helpers ----------------
__device__ __forceinline__ ull pk2(float x) {
    ull u; asm("mov.b64 %0, {%1, %1};" : "=l"(u) : "r"(__float_as_uint(x))); return u;
}
__device__ __forceinline__ void ffma2(ull& d, ull a, ull b) {
    asm("fma.rn.f32x2 %0, %1, %2, %0;" : "+l"(d) : "l"(a), "l"(b));
}
__device__ __forceinline__ float2 upk(ull u) {
    float2 f; asm("mov.b64 {%0, %1}, %2;" : "=f"(f.x), "=f"(f.y) : "l"(u)); return f;
}
__device__ __forceinline__ void red2(float* p, float a, float b) {
    asm volatile("red.global.add.v2.f32 [%0], {%1, %2};"
                 :: "l"(p), "f"(a), "f"(b) : "memory");
}
__device__ __forceinline__ void red1(float* p, float a) {
    asm volatile("red.global.add.f32 [%0], %1;" :: "l"(p), "f"(a) : "memory");
}
__device__ __forceinline__ void redmax(uint32_t* p, uint32_t v) {
    asm volatile("red.global.max.u32 [%0], %1;" :: "l"(p), "r"(v) : "memory");
}
__device__ __forceinline__ float ex2f(float x) {
    float r; asm("ex2.approx.f32 %0, %1;" : "=f"(r) : "f"(x)); return r;
}
__device__ __forceinline__ void mma16(float* d, const uint32_t* a, uint32_t b0, uint32_t b1) {
    asm volatile("mma.sync.aligned.m16n8k16.row.col.f32.f16.f16.f32 "
                 "{%0,%1,%2,%3}, {%4,%5,%6,%7}, {%8,%9}, {%0,%1,%2,%3};"
                 : "+f"(d[0]), "+f"(d[1]), "+f"(d[2]), "+f"(d[3])
                 : "r"(a[0]), "r"(a[1]), "r"(a[2]), "r"(a[3]), "r"(b0), "r"(b1));
}

// ---------------- launch 1: h = input@W + f1/f2 + red.max + B pack + S zero ----------------
__global__ void __launch_bounds__(256) k_h(const float* __restrict__ input,
                                           const float* __restrict__ W,
                                           const float* __restrict__ a) {
    extern __shared__ float sm[];
    float* in_s = sm;               // [64][260] during GEMM; reused as tile after
    float* W_s  = sm + 64 * 260;    // [256][64]
    int t = threadIdx.x;
    int rowBase = blockIdx.x * 64;

    // zero S for this block's 64 rows (strictly precedes k_attn's red1)
    if (t < 16)
        reinterpret_cast<float4*>(g_S)[blockIdx.x * 16 + t] =
            make_float4(0.f, 0.f, 0.f, 0.f);

#pragma unroll
    for (int m = 0; m < 16; m++) {
        int idx4 = t + 256 * m;
        *reinterpret_cast<float4*>(&W_s[4 * idx4]) =
            *reinterpret_cast<const float4*>(&W[4 * idx4]);
    }
#pragma unroll
    for (int m = 0; m < 16; m++) {
        int idx4 = t + 256 * m;
        int r = idx4 >> 6, k4 = (idx4 & 63) * 4;
        *reinterpret_cast<float4*>(&in_s[r * 260 + k4]) =
            *reinterpret_cast<const float4*>(&input[(size_t)(rowBase + r) * IND + k4]);
    }
    __syncthreads();

    int ty = t >> 3, tx = t & 7;
    ull acc[2][4];
#pragma unroll
    for (int r = 0; r < 2; r++)
#pragma unroll
        for (int g = 0; g < 4; g++) acc[r][g] = 0ull;

#pragma unroll 8
    for (int k = 0; k < IND; k++) {
        ulonglong2 wa = *reinterpret_cast<const ulonglong2*>(&W_s[k * 64 + 4 * tx]);
        ulonglong2 wb = *reinterpret_cast<const ulonglong2*>(&W_s[k * 64 + 32 + 4 * tx]);
#pragma unroll
        for (int r = 0; r < 2; r++) {
            ull iv = pk2(in_s[(2 * ty + r) * 260 + k]);
            ffma2(acc[r][0], iv, wa.x); ffma2(acc[r][1], iv, wa.y);
            ffma2(acc[r][2], iv, wb.x); ffma2(acc[r][3], iv, wb.y);
        }
    }

    float4 A1a = *reinterpret_cast<const float4*>(&a[4 * tx]);
    float4 A1b = *reinterpret_cast<const float4*>(&a[32 + 4 * tx]);
    float4 A2a = *reinterpret_cast<const float4*>(&a[OUTD + 4 * tx]);
    float4 A2b = *reinterpret_cast<const float4*>(&a[OUTD + 32 + 4 * tx]);

    // reuse smem: tile[64][65] for h transpose, f2s[64] for scaled f2
    float* tile = sm;               // 64*65 = 4160 floats
    float* f2s  = sm + 64 * 65;     // 64 floats

    __syncthreads();   // all reads of in_s/W_s complete before overwrite

#pragma unroll
    for (int r = 0; r < 2; r++) {
        int lrow = 2 * ty + r;                 // local row 0..63
        int row  = rowBase + lrow;
        float2 p0 = upk(acc[r][0]), p1 = upk(acc[r][1]);
        float2 p2 = upk(acc[r][2]), p3 = upk(acc[r][3]);

        float* tr = &tile[lrow * 65];
        tr[4 * tx]     = p0.x; tr[4 * tx + 1] = p0.y;
        tr[4 * tx + 2] = p1.x; tr[4 * tx + 3] = p1.y;
        tr[32 + 4 * tx]     = p2.x; tr[32 + 4 * tx + 1] = p2.y;
        tr[32 + 4 * tx + 2] = p3.x; tr[32 + 4 * tx + 3] = p3.y;

        float s1 = p0.x * A1a.x + p0.y * A1a.y + p1.x * A1a.z + p1.y * A1a.w
                 + p2.x * A1b.x + p2.y * A1b.y + p3.x * A1b.z + p3.y * A1b.w;
        float s2 = p0.x * A2a.x + p0.y * A2a.y + p1.x * A2a.z + p1.y * A2a.w
                 + p2.x * A2b.x + p2.y * A2b.y + p3.x * A2b.z + p3.y * A2b.w;
#pragma unroll
        for (int off = 1; off < 8; off <<= 1) {
            s1 += __shfl_xor_sync(0xFFFFFFFFu, s1, off);
            s2 += __shfl_xor_sync(0xFFFFFFFFu, s2, off);
        }
        if (tx == 0) {
            g_f1[row]  = s1;
            g_f1L[row] = s1 * L2E;
            g_f2[row]  = s2;
            f2s[lrow]  = s2 * L2E;
            uint32_t u = __float_as_uint(s2);
            uint32_t key = u ^ (uint32_t)(((int)u >> 31) | 0x80000000);
            redmax(&g_maxkey, key);
        }
    }
    __syncthreads();

    int jBase = rowBase;   // these 64 rows are j-rows for the pack

    // f2p (permuted): g_f2p[j16*4 + fc] = {f2L[j16*16+4fc+0..3]}
    if (t < 16) {
        int j16r = t >> 2, fc = t & 3;
        int j = j16r * 16 + 4 * fc;
        float4 v;
        v.x = f2s[j]; v.y = f2s[j + 1]; v.z = f2s[j + 2]; v.w = f2s[j + 3];
        g_f2p[(jBase / 16 + j16r) * 4 + fc] = v;
    }

    // pack B fragments (permuted, uint4 pairs q/q+4)
#pragma unroll
    for (int m = 0; m < 2; m++) {
        int idx = t + 256 * m;            // 0..511 = j16r(4) x qq(4) x lane(32)
        int j16r = idx >> 7;
        int qq   = (idx >> 5) & 3;
        int lane = idx & 31;
        int fr = lane >> 2, fc = lane & 3;
        int j0 = j16r * 16 + 4 * fc;
        int n1 = qq * 8 + fr;
        int n2 = (qq + 4) * 8 + fr;
        __half2 lo1 = __floats2half2_rn(tile[j0 * 65 + n1],       tile[(j0 + 1) * 65 + n1]);
        __half2 hi1 = __floats2half2_rn(tile[(j0 + 2) * 65 + n1], tile[(j0 + 3) * 65 + n1]);
        __half2 lo2 = __floats2half2_rn(tile[j0 * 65 + n2],       tile[(j0 + 1) * 65 + n2]);
        __half2 hi2 = __floats2half2_rn(tile[(j0 + 2) * 65 + n2], tile[(j0 + 3) * 65 + n2]);
        uint4 pkt;
        pkt.x = *reinterpret_cast<uint32_t*>(&lo1);
        pkt.y = *reinterpret_cast<uint32_t*>(&hi1);
        pkt.z = *reinterpret_cast<uint32_t*>(&lo2);
        pkt.w = *reinterpret_cast<uint32_t*>(&hi2);
        g_hB4[((jBase / 16 + j16r) * 4 + qq) * 32 + lane] = pkt;
    }
}

// ---------------- launch 2: smem-B register-fragment attention (unchanged) ----------------
__global__ void __launch_bounds__(256, 3) k_attn(const int* __restrict__ adj) {
    __shared__ uint4  sB[2048];   // 32KB B fragments for this block's 256 j
    __shared__ float4 sF[64];     // 1KB  f2p

    int t = threadIdx.x;
    int wid = t >> 5, lane = t & 31;
    int fr = lane >> 2, fc = lane & 3;
    int mrow   = blockIdx.y * 128 + wid * 16;
    int jStart = blockIdx.x * JSPL;

    // stage B + f2 tiles (one-time, L2-resident source)
    {
        const uint4* gB = g_hB4 + (size_t)(jStart / 16) * 128;
#pragma unroll
        for (int m = 0; m < 8; m++) sB[t + 256 * m] = gB[t + 256 * m];
        if (t < 64) sF[t] = g_f2p[(size_t)(jStart / 16) * 4 + t];
    }

    // decode global max f2 (log2 space) from the order-preserving key
    float mL;
    {
        uint32_t k = g_maxkey;
        uint32_t u = (k & 0x80000000u) ? (k ^ 0x80000000u) : ~k;
        mL = __uint_as_float(u) * L2E;
    }

    // per-lane row constants (log2 space)
    float f1L0 = g_f1L[mrow + fr];
    float f1L1 = g_f1L[mrow + fr + 8];
    float y0 = f1L0 + mL, y1 = f1L1 + mL;
    float ci0 = fmaxf(y0, 0.01f * y0);    // row max of lrelu (exact; lrelu monotone)
    float ci1 = fmaxf(y1, 0.01f * y1);

    const int4* pr0 = reinterpret_cast<const int4*>(adj + (size_t)(mrow + fr) * N_ + jStart) + fc;
    const int4* pr1 = reinterpret_cast<const int4*>(adj + (size_t)(mrow + fr + 8) * N_ + jStart) + fc;

    float accv[8][4];
#pragma unroll
    for (int q = 0; q < 8; q++)
#pragma unroll
        for (int g = 0; g < 4; g++) accv[q][g] = 0.f;
    float accs[4] = {0.f, 0.f, 0.f, 0.f};

    const uint32_t bone = (fr == 0) ? 0x3C003C00u : 0u;   // ones-column B tile

    // adj for chunk 0 / kk 0
    int4 avA0 = __ldcs(pr0), avA1 = __ldcs(pr1);
    __syncthreads();

    // e = 2^(lrelu(f1+f2) - ci) in (0,1]; masked slots zeroed by half2 AND
    // (adj is exactly {0,1}: msk = x*0xFFFF + y*0xFFFF0000)
#define GEN_A(AREG, AVA, AVB, FV)                                                 \
    do {                                                                          \
        float e00, e01, e02, e03, e10, e11, e12, e13;                             \
        { float y = f1L0 + (FV).x; e00 = ex2f(fmaxf(y - ci0, fmaf(y, 0.01f, -ci0))); } \
        { float y = f1L0 + (FV).y; e01 = ex2f(fmaxf(y - ci0, fmaf(y, 0.01f, -ci0))); } \
        { float y = f1L0 + (FV).z; e02 = ex2f(fmaxf(y - ci0, fmaf(y, 0.01f, -ci0))); } \
        { float y = f1L0 + (FV).w; e03 = ex2f(fmaxf(y - ci0, fmaf(y, 0.01f, -ci0))); } \
        { float y = f1L1 + (FV).x; e10 = ex2f(fmaxf(y - ci1, fmaf(y, 0.01f, -ci1))); } \
        { float y = f1L1 + (FV).y; e11 = ex2f(fmaxf(y - ci1, fmaf(y, 0.01f, -ci1))); } \
        { float y = f1L1 + (FV).z; e12 = ex2f(fmaxf(y - ci1, fmaf(y, 0.01f, -ci1))); } \
        { float y = f1L1 + (FV).w; e13 = ex2f(fmaxf(y - ci1, fmaf(y, 0.01f, -ci1))); } \
        __half2 h0 = __floats2half2_rn(e00, e01);                                 \
        __half2 h1 = __floats2half2_rn(e10, e11);                                 \
        __half2 h2 = __floats2half2_rn(e02, e03);                                 \
        __half2 h3 = __floats2half2_rn(e12, e13);                                 \
        uint32_t mA0 = (uint32_t)(AVA).x * 0xFFFFu + (uint32_t)(AVA).y * 0xFFFF0000u; \
        uint32_t mA1 = (uint32_t)(AVA).z * 0xFFFFu + (uint32_t)(AVA).w * 0xFFFF0000u; \
        uint32_t mB0 = (uint32_t)(AVB).x * 0xFFFFu + (uint32_t)(AVB).y * 0xFFFF0000u; \
        uint32_t mB1 = (uint32_t)(AVB).z * 0xFFFFu + (uint32_t)(AVB).w * 0xFFFF0000u; \
        (AREG)[0] = *reinterpret_cast<uint32_t*>(&h0) & mA0;                      \
        (AREG)[1] = *reinterpret_cast<uint32_t*>(&h1) & mB0;                      \
        (AREG)[2] = *reinterpret_cast<uint32_t*>(&h2) & mA1;                      \
        (AREG)[3] = *reinterpret_cast<uint32_t*>(&h3) & mB1;                      \
    } while (0)

#pragma unroll 2
    for (int ch = 0; ch < CH; ch++) {
        // prefetch kk1 adj (used ~60 instrs later)
        int4 avB0 = __ldcs(pr0 + 4), avB1 = __ldcs(pr1 + 4);

        // ---- kk = 0 ----
        {
            uint4 bq[4];
#pragma unroll
            for (int qq = 0; qq < 4; qq++) bq[qq] = sB[ch * 256 + qq * 32 + lane];
            float4 fv = sF[ch * 8 + fc];
            uint32_t a[4];
            GEN_A(a, avA0, avA1, fv);
#pragma unroll
            for (int qq = 0; qq < 4; qq++) {
                mma16(accv[qq],     a, bq[qq].x, bq[qq].y);
                mma16(accv[qq + 4], a, bq[qq].z, bq[qq].w);
            }
            mma16(accs, a, bone, bone);
        }

        // prefetch next chunk's kk0 adj
        if (ch + 1 < CH) { avA0 = __ldcs(pr0 + 8); avA1 = __ldcs(pr1 + 8); }

        // ---- kk = 1 ----
        {
            uint4 bq[4];
#pragma unroll
            for (int qq = 0; qq < 4; qq++) bq[qq] = sB[ch * 256 + 128 + qq * 32 + lane];
            float4 fv = sF[ch * 8 + 4 + fc];
            uint32_t a[4];
            GEN_A(a, avB0, avB1, fv);
#pragma unroll
            for (int qq = 0; qq < 4; qq++) {
                mma16(accv[qq],     a, bq[qq].x, bq[qq].y);
                mma16(accv[qq + 4], a, bq[qq].z, bq[qq].w);
            }
            mma16(accs, a, bone, bone);
        }

        pr0 += 8; pr1 += 8;
    }
#undef GEN_A

    // epilogue: numerators
#pragma unroll
    for (int q = 0; q < 8; q++) {
        int col = q * 8 + 2 * fc;
        red2(&g_V[(mrow + fr) * OUTD + col],     accv[q][0], accv[q][1]);
        red2(&g_V[(mrow + fr + 8) * OUTD + col], accv[q][2], accv[q][3]);
    }
    // denominators
    if (fc == 0) {
        red1(&g_S[mrow + fr],     accs[0]);
        red1(&g_S[mrow + fr + 8], accs[2]);
    }
}

// ---------------- launch 3: normalize + scalar outputs + state restore ----------------
__global__ void __launch_bounds__(256) k_fin(float* __restrict__ out) {
    int gid = blockIdx.x * blockDim.x + threadIdx.x;   // 0..131071 float4s
    float4 v = reinterpret_cast<const float4*>(g_V)[gid];
    float  s = g_S[gid >> 4];                          // 16 float4 per row
    float  inv = 1.0f / s;
    reinterpret_cast<float4*>(out)[gid] =
        make_float4(v.x * inv, v.y * inv, v.z * inv, v.w * inv);
    // restore V invariant for the next graph replay (same thread, same address)
    reinterpret_cast<float4*>(g_V)[gid] = make_float4(0.f, 0.f, 0.f, 0.f);
    if (gid < 3) {
        float x;
        if (gid == 0)      x = g_f1[1] + g_f2[2];   // face_Rhand = e[1,2]
        else if (gid == 1) x = g_f1[1] + g_f2[3];   // face_Lhand = e[1,3]
        else               x = g_f1[3] + g_f2[2];   // Rhand_Lhand = e[3,2]
        out[N_ * OUTD + gid] = fmaxf(x, 0.01f * x);
    }
    if (gid == 4) g_maxkey = 0u;                    // restore for next replay
}

// ---------------- launch ----------------
extern "C" void kernel_launch(void* const* d_in, const int* in_sizes, int n_in,
                              void* d_out, int out_size) {
    const float* input = (const float*)d_in[0];
    const int*   adj   = (const int*)  d_in[1];
    const float* W     = (const float*)d_in[2];
    const float* a     = (const float*)d_in[3];
    float*       out   = (float*)d_out;
    (void)in_sizes; (void)n_in; (void)out_size;

    const int smem_h = (64 * 260 + 256 * 64) * 4;   // 132096 B (pack phase reuses it)
    cudaFuncSetAttribute(k_h, cudaFuncAttributeMaxDynamicSharedMemorySize, smem_h);

    k_h   <<<128, 256, smem_h>>>(input, W, a);
    k_attn<<<dim3(NS, N_ / 128), 256>>>(adj);
    k_fin <<<512, 256>>>(out);
}